// round 7
// baseline (speedup 1.0000x reference)
#include <cuda_runtime.h>
#include <cuda_bf16.h>
#include <cstdint>
#include <math.h>
#include <float.h>

#define MDIM   4096
#define KDIM   1024
#define VOCABN 32000
#define NBITS  15

// ---------------- scratch: bf16 hi/lo splits --------------------------------
__device__ __nv_bfloat16 g_Ahi[(size_t)MDIM * KDIM];
__device__ __nv_bfloat16 g_Alo[(size_t)MDIM * KDIM];
__device__ __nv_bfloat16 g_Bhi[(size_t)VOCABN * KDIM];
__device__ __nv_bfloat16 g_Blo[(size_t)VOCABN * KDIM];

__device__ __forceinline__ uint32_t smem_u32(const void* p) {
    uint32_t a;
    asm("{ .reg .u64 t; cvta.to.shared.u64 t, %1; cvt.u32.u64 %0, t; }"
        : "=r"(a) : "l"(p));
    return a;
}
#define SW128(o) ((o) ^ (((o) >> 3) & 0x70))

// ---------------- split kernels ---------------------------------------------
__device__ __forceinline__ void split4(float4 v, ushort4& h4, ushort4& l4) {
    __nv_bfloat16 h;
    h = __float2bfloat16(v.x); h4.x = __bfloat16_as_ushort(h);
    l4.x = __bfloat16_as_ushort(__float2bfloat16(v.x - __bfloat162float(h)));
    h = __float2bfloat16(v.y); h4.y = __bfloat16_as_ushort(h);
    l4.y = __bfloat16_as_ushort(__float2bfloat16(v.y - __bfloat162float(h)));
    h = __float2bfloat16(v.z); h4.z = __bfloat16_as_ushort(h);
    l4.z = __bfloat16_as_ushort(__float2bfloat16(v.z - __bfloat162float(h)));
    h = __float2bfloat16(v.w); h4.w = __bfloat16_as_ushort(h);
    l4.w = __bfloat16_as_ushort(__float2bfloat16(v.w - __bfloat162float(h)));
}
__global__ __launch_bounds__(256) void split_A_kernel(const float* __restrict__ src) {
    int i = blockIdx.x * 256 + threadIdx.x;
    ushort4 h4, l4; split4(((const float4*)src)[i], h4, l4);
    ((ushort4*)g_Ahi)[i] = h4; ((ushort4*)g_Alo)[i] = l4;
}
__global__ __launch_bounds__(256) void split_B_kernel(const float* __restrict__ src) {
    int i = blockIdx.x * 256 + threadIdx.x;
    ushort4 h4, l4; split4(((const float4*)src)[i], h4, l4);
    ((ushort4*)g_Bhi)[i] = h4; ((ushort4*)g_Blo)[i] = l4;
}

// ---------------- embed: gather + bit combo ---------------------------------
__global__ __launch_bounds__(256) void embed_kernel(
    const int* __restrict__ ids, const float* __restrict__ weight,
    const float* __restrict__ weight_bit,
    float* __restrict__ out_id, float* __restrict__ out_bit)
{
    const int t = blockIdx.x;
    const int id = ids[t];
    const int d = threadIdx.x * 4;
    float4 w = *(const float4*)(weight + (size_t)id * KDIM + d);
    *(float4*)(out_id + (size_t)t * KDIM + d) = w;
    float4 acc = make_float4(0.f, 0.f, 0.f, 0.f);
#pragma unroll
    for (int j = 0; j < NBITS; j++) {
        const float s = ((id >> (NBITS - 1 - j)) & 1) ? 1.0f : -1.0f;
        float4 wb = *(const float4*)(weight_bit + j * KDIM + d);
        acc.x = fmaf(s, wb.x, acc.x); acc.y = fmaf(s, wb.y, acc.y);
        acc.z = fmaf(s, wb.z, acc.z); acc.w = fmaf(s, wb.w, acc.w);
    }
    *(float4*)(out_bit + (size_t)t * KDIM + d) = acc;
}

// ---------------- bf16x3 GEMM via mma.sync ----------------------------------
// C[4096,32000] = A[4096,1024] @ B[32000,1024]^T
// CTA 128x256, 512 threads, 16 warps as 4Mx4N of 32x64 warp tiles.
// 4 warps/SMSP for tensor-pipe latency coverage; <=128 regs/thread.
#define BM 128
#define BN 256
#define BK 64
#define TILE_A (BM * BK * 2)            // 16 KB
#define TILE_Bt (BN * BK * 2)           // 32 KB
#define OFF_ALO TILE_A
#define OFF_BHI (2 * TILE_A)
#define OFF_BLO (2 * TILE_A + TILE_Bt)
#define STAGE_B (2 * TILE_A + 2 * TILE_Bt)  // 96 KB
#define GEMM_SMEM (2 * STAGE_B)             // 192 KB

#define CP16(dst, src) \
    asm volatile("cp.async.cg.shared.global [%0], [%1], 16;" \
                 :: "r"(dst), "l"(src) : "memory")
#define LDSM4(r0, r1, r2, r3, a) \
    asm volatile("ldmatrix.sync.aligned.m8n8.x4.shared.b16 {%0,%1,%2,%3}, [%4];" \
                 : "=r"(r0), "=r"(r1), "=r"(r2), "=r"(r3) : "r"(a))
#define MMA16816(d, a, b0, b1) \
    asm volatile("mma.sync.aligned.m16n8k16.row.col.f32.bf16.bf16.f32 " \
                 "{%0,%1,%2,%3}, {%4,%5,%6,%7}, {%8,%9}, {%0,%1,%2,%3};" \
                 : "+f"((d)[0]), "+f"((d)[1]), "+f"((d)[2]), "+f"((d)[3]) \
                 : "r"((a)[0]), "r"((a)[1]), "r"((a)[2]), "r"((a)[3]), \
                   "r"(b0), "r"(b1))

__global__ __launch_bounds__(512, 1) void gemm_kernel(float* __restrict__ C)
{
    extern __shared__ char smem[];
    const uint32_t sb = smem_u32(smem);
    const int tid = threadIdx.x, wid = tid >> 5, lane = tid & 31;
    const int bm = blockIdx.x * BM, bn = blockIdx.y * BN;
    const int wm = (wid & 3) * 32;      // 4 warps in M
    const int wn = (wid >> 2) * 64;     // 4 warps in N

    const __nv_bfloat16* gAh = g_Ahi + (size_t)bm * KDIM;
    const __nv_bfloat16* gAl = g_Alo + (size_t)bm * KDIM;
    const __nv_bfloat16* gBh = g_Bhi + (size_t)bn * KDIM;
    const __nv_bfloat16* gBl = g_Blo + (size_t)bn * KDIM;

    const int NK = KDIM / BK;           // 16

    auto load_stage = [&](int kt, int stg) {
        const uint32_t base = sb + stg * STAGE_B;
        const int ke = kt * BK;
        // A tiles: 1024 chunks -> 2 per thread
#pragma unroll
        for (int i = 0; i < 2; i++) {
            const int chunk = i * 512 + tid;
            const int row = chunk >> 3;
            const int kc = chunk & 7;
            const uint32_t d = SW128(row * 128 + kc * 16);
            const size_t so = (size_t)row * KDIM + ke + kc * 8;
            CP16(base + d,           gAh + so);
            CP16(base + OFF_ALO + d, gAl + so);
        }
        // B tiles: 2048 chunks -> 4 per thread
#pragma unroll
        for (int i = 0; i < 4; i++) {
            const int chunk = i * 512 + tid;
            const int row = chunk >> 3;
            const int kc = chunk & 7;
            const uint32_t d = SW128(row * 128 + kc * 16);
            const size_t so = (size_t)row * KDIM + ke + kc * 8;
            CP16(base + OFF_BHI + d, gBh + so);
            CP16(base + OFF_BLO + d, gBl + so);
        }
        asm volatile("cp.async.commit_group;" ::: "memory");
    };

    load_stage(0, 0);
    load_stage(1, 1);

    float acc[2][8][4] = {};            // 64 regs

    const int lrow = lane & 15;
    const int lkb  = (lane >> 4) * 16;
    int offA[2], offB[4];
#pragma unroll
    for (int mt = 0; mt < 2; mt++) offA[mt] = (wm + mt * 16 + lrow) * 128 + lkb;
#pragma unroll
    for (int nt = 0; nt < 4; nt++) offB[nt] = (wn + nt * 16 + lrow) * 128 + lkb;

    for (int kt = 0; kt < NK; kt++) {
        asm volatile("cp.async.wait_group 1;" ::: "memory");
        __syncthreads();
        const uint32_t base = sb + (kt & 1) * STAGE_B;

#pragma unroll
        for (int ks = 0; ks < 4; ks++) {
            uint32_t ah[2][4], al[2][4];     // 16 regs
#pragma unroll
            for (int mt = 0; mt < 2; mt++) {
                const uint32_t a = base + SW128(offA[mt] + ks * 32);
                LDSM4(ah[mt][0], ah[mt][1], ah[mt][2], ah[mt][3], a);
                LDSM4(al[mt][0], al[mt][1], al[mt][2], al[mt][3], a + OFF_ALO);
            }
            uint32_t b[4][4];                // 16 regs, reused BHI -> BLO
#pragma unroll
            for (int nt = 0; nt < 4; nt++) {
                const uint32_t ba = base + SW128(offB[nt] + ks * 32);
                LDSM4(b[nt][0], b[nt][1], b[nt][2], b[nt][3], ba + OFF_BHI);
            }
            // hh + lh passes (B_hi live)
#pragma unroll
            for (int mt = 0; mt < 2; mt++)
#pragma unroll
                for (int nt = 0; nt < 4; nt++) {
                    MMA16816(acc[mt][2 * nt + 0], ah[mt], b[nt][0], b[nt][2]);
                    MMA16816(acc[mt][2 * nt + 1], ah[mt], b[nt][1], b[nt][3]);
                }
#pragma unroll
            for (int mt = 0; mt < 2; mt++)
#pragma unroll
                for (int nt = 0; nt < 4; nt++) {
                    MMA16816(acc[mt][2 * nt + 0], al[mt], b[nt][0], b[nt][2]);
                    MMA16816(acc[mt][2 * nt + 1], al[mt], b[nt][1], b[nt][3]);
                }
            // reload b with B_lo, hl pass
#pragma unroll
            for (int nt = 0; nt < 4; nt++) {
                const uint32_t ba = base + SW128(offB[nt] + ks * 32);
                LDSM4(b[nt][0], b[nt][1], b[nt][2], b[nt][3], ba + OFF_BLO);
            }
#pragma unroll
            for (int mt = 0; mt < 2; mt++)
#pragma unroll
                for (int nt = 0; nt < 4; nt++) {
                    MMA16816(acc[mt][2 * nt + 0], ah[mt], b[nt][0], b[nt][2]);
                    MMA16816(acc[mt][2 * nt + 1], ah[mt], b[nt][1], b[nt][3]);
                }
        }
        __syncthreads();
        if (kt + 2 < NK) load_stage(kt + 2, kt & 1);
    }

    // epilogue
    const int er = lane >> 2, ec = (lane & 3) * 2;
#pragma unroll
    for (int mt = 0; mt < 2; mt++) {
#pragma unroll
        for (int nt = 0; nt < 8; nt++) {
            float* c0 = C + (size_t)(bm + wm + mt * 16 + er) * VOCABN
                          + bn + wn + nt * 8 + ec;
            *(float2*)c0 = make_float2(acc[mt][nt][0], acc[mt][nt][1]);
            float* c1 = c0 + (size_t)8 * VOCABN;
            *(float2*)c1 = make_float2(acc[mt][nt][2], acc[mt][nt][3]);
        }
    }
}

// ---------------- thresholded softmax + bit projection ----------------------
__global__ __launch_bounds__(256) void softmax_bits_kernel(
    const float* __restrict__ logit, float* __restrict__ logit_w)
{
    const int row = blockIdx.x;
    const int tid = threadIdx.x;
    const float4* x4 = (const float4*)(logit + (size_t)row * VOCABN);

    float m = -FLT_MAX;
    for (int i = tid; i < VOCABN / 4; i += 256) {
        float4 v = x4[i];
        m = fmaxf(m, fmaxf(fmaxf(v.x, v.y), fmaxf(v.z, v.w)));
    }
#pragma unroll
    for (int o = 16; o; o >>= 1) m = fmaxf(m, __shfl_xor_sync(0xffffffffu, m, o));
    __shared__ float smax[8];
    if ((tid & 31) == 0) smax[tid >> 5] = m;
    __syncthreads();
    float mm = smax[0];
#pragma unroll
    for (int w = 1; w < 8; w++) mm = fmaxf(mm, smax[w]);

    const float thr = mm - 20.0f;
    float Z = 0.f, S[NBITS];
#pragma unroll
    for (int k = 0; k < NBITS; k++) S[k] = 0.f;

    for (int i = tid; i < VOCABN / 4; i += 256) {
        float4 v = x4[i];
        const float c[4] = {v.x, v.y, v.z, v.w};
#pragma unroll
        for (int j = 0; j < 4; j++) {
            if (c[j] > thr) {
                const float e = __expf(c[j] - mm);
                Z += e;
                const int vv = i * 4 + j;
#pragma unroll
                for (int k = 0; k < NBITS; k++)
                    if ((vv >> (NBITS - 1 - k)) & 1) S[k] += e;
            }
        }
    }
#pragma unroll
    for (int o = 16; o; o >>= 1) {
        Z += __shfl_xor_sync(0xffffffffu, Z, o);
#pragma unroll
        for (int k = 0; k < NBITS; k++)
            S[k] += __shfl_xor_sync(0xffffffffu, S[k], o);
    }
    __shared__ float red[16][8];
    __shared__ float sfin[16];
    if ((tid & 31) == 0) {
        const int w = tid >> 5;
#pragma unroll
        for (int k = 0; k < NBITS; k++) red[k][w] = S[k];
        red[NBITS][w] = Z;
    }
    __syncthreads();
    if (tid < 16) {
        float s = 0.f;
#pragma unroll
        for (int w = 0; w < 8; w++) s += red[tid][w];
        sfin[tid] = s;
    }
    __syncthreads();
    if (tid < NBITS) {
        const float Zt = sfin[NBITS];
        logit_w[(size_t)row * NBITS + tid] = (2.f * sfin[tid] - Zt) / Zt;
    }
}

// ---------------- launch ----------------------------------------------------
extern "C" void kernel_launch(void* const* d_in, const int* in_sizes, int n_in,
                              void* d_out, int out_size)
{
    const int*   ids        = (const int*)  d_in[0];
    const float* tensor     = (const float*)d_in[1];
    const float* weight     = (const float*)d_in[2];
    const float* weight_bit = (const float*)d_in[3];

    float* out       = (float*)d_out;
    float* out_id    = out;
    float* out_bit   = out + (size_t)MDIM * KDIM;
    float* out_logit = out + (size_t)2 * MDIM * KDIM;
    float* out_lw    = out_logit + (size_t)MDIM * VOCABN;

    cudaFuncSetAttribute(gemm_kernel,
                         cudaFuncAttributeMaxDynamicSharedMemorySize, GEMM_SMEM);

    embed_kernel<<<MDIM, 256>>>(ids, weight, weight_bit, out_id, out_bit);
    split_A_kernel<<<MDIM * KDIM / 1024, 256>>>(tensor);
    split_B_kernel<<<VOCABN * KDIM / 1024, 256>>>(weight);

    dim3 grid(MDIM / BM, VOCABN / BN);  // M fastest -> B-slice L2 reuse
    gemm_kernel<<<grid, 512, GEMM_SMEM>>>(out_logit);

    softmax_bits_kernel<<<MDIM, 256>>>(out_logit, out_lw);
}

// round 10
// speedup vs baseline: 1.3136x; 1.3136x over previous
#include <cuda_runtime.h>
#include <cuda_fp16.h>
#include <cstdint>
#include <math.h>
#include <float.h>

#define MDIM   4096
#define KDIM   1024
#define VOCABN 32000
#define NBITS  15

// ---------------- scratch: fp16 splits (A hi/lo, B hi only) -----------------
__device__ __half g_Ahi[(size_t)MDIM * KDIM];
__device__ __half g_Alo[(size_t)MDIM * KDIM];
__device__ __half g_Bhi[(size_t)VOCABN * KDIM];

__device__ __forceinline__ uint32_t smem_u32(const void* p) {
    uint32_t a;
    asm("{ .reg .u64 t; cvta.to.shared.u64 t, %1; cvt.u32.u64 %0, t; }"
        : "=r"(a) : "l"(p));
    return a;
}
#define SW128(o) ((o) ^ (((o) >> 3) & 0x70))

// ---------------- split kernels ---------------------------------------------
__global__ __launch_bounds__(256) void split_A_kernel(const float* __restrict__ src) {
    int i = blockIdx.x * 256 + threadIdx.x;          // float4 index
    float4 v = ((const float4*)src)[i];
    ushort4 h4, l4;
    __half h;
    h = __float2half_rn(v.x); h4.x = __half_as_ushort(h);
    l4.x = __half_as_ushort(__float2half_rn(v.x - __half2float(h)));
    h = __float2half_rn(v.y); h4.y = __half_as_ushort(h);
    l4.y = __half_as_ushort(__float2half_rn(v.y - __half2float(h)));
    h = __float2half_rn(v.z); h4.z = __half_as_ushort(h);
    l4.z = __half_as_ushort(__float2half_rn(v.z - __half2float(h)));
    h = __float2half_rn(v.w); h4.w = __half_as_ushort(h);
    l4.w = __half_as_ushort(__float2half_rn(v.w - __half2float(h)));
    ((ushort4*)g_Ahi)[i] = h4;
    ((ushort4*)g_Alo)[i] = l4;
}
__global__ __launch_bounds__(256) void split_B_kernel(const float* __restrict__ src) {
    int i = blockIdx.x * 256 + threadIdx.x;
    float4 v = ((const float4*)src)[i];
    ushort4 h4;
    h4.x = __half_as_ushort(__float2half_rn(v.x));
    h4.y = __half_as_ushort(__float2half_rn(v.y));
    h4.z = __half_as_ushort(__float2half_rn(v.z));
    h4.w = __half_as_ushort(__float2half_rn(v.w));
    ((ushort4*)g_Bhi)[i] = h4;
}

// ---------------- embed: gather + bit combo ---------------------------------
__global__ __launch_bounds__(256) void embed_kernel(
    const int* __restrict__ ids, const float* __restrict__ weight,
    const float* __restrict__ weight_bit,
    float* __restrict__ out_id, float* __restrict__ out_bit)
{
    const int t = blockIdx.x;
    const int id = ids[t];
    const int d = threadIdx.x * 4;
    float4 w = *(const float4*)(weight + (size_t)id * KDIM + d);
    *(float4*)(out_id + (size_t)t * KDIM + d) = w;
    float4 acc = make_float4(0.f, 0.f, 0.f, 0.f);
#pragma unroll
    for (int j = 0; j < NBITS; j++) {
        const float s = ((id >> (NBITS - 1 - j)) & 1) ? 1.0f : -1.0f;
        float4 wb = *(const float4*)(weight_bit + j * KDIM + d);
        acc.x = fmaf(s, wb.x, acc.x); acc.y = fmaf(s, wb.y, acc.y);
        acc.z = fmaf(s, wb.z, acc.z); acc.w = fmaf(s, wb.w, acc.w);
    }
    *(float4*)(out_bit + (size_t)t * KDIM + d) = acc;
}

// ---------------- fp16x2 GEMM via mma.sync ----------------------------------
// C[4096,32000] = (Ahi+Alo)[4096,1024] @ Bhi[32000,1024]^T
// CTA 128x256, 256 threads, warp tile 64x64 (2Mx4N), BK=64.
// 3-stage cp.async pipeline, leading loads, ONE barrier per k-tile.
#define BM 128
#define BN 256
#define BK 64
#define NSTAGE 3
#define TILE_A (BM * BK * 2)            // 16 KB
#define TILE_Bt (BN * BK * 2)           // 32 KB
#define OFF_ALO TILE_A                  // 16 KB
#define OFF_BHI (2 * TILE_A)            // 32 KB
#define STAGE_B (2 * TILE_A + TILE_Bt)  // 64 KB
#define GEMM_SMEM (NSTAGE * STAGE_B)    // 192 KB

#define CP16(dst, src) \
    asm volatile("cp.async.cg.shared.global [%0], [%1], 16;" \
                 :: "r"(dst), "l"(src) : "memory")
#define LDSM4(r0, r1, r2, r3, a) \
    asm volatile("ldmatrix.sync.aligned.m8n8.x4.shared.b16 {%0,%1,%2,%3}, [%4];" \
                 : "=r"(r0), "=r"(r1), "=r"(r2), "=r"(r3) : "r"(a))
#define MMA16816(d, a, b0, b1) \
    asm volatile("mma.sync.aligned.m16n8k16.row.col.f32.f16.f16.f32 " \
                 "{%0,%1,%2,%3}, {%4,%5,%6,%7}, {%8,%9}, {%0,%1,%2,%3};" \
                 : "+f"((d)[0]), "+f"((d)[1]), "+f"((d)[2]), "+f"((d)[3]) \
                 : "r"((a)[0]), "r"((a)[1]), "r"((a)[2]), "r"((a)[3]), \
                   "r"(b0), "r"(b1))

__global__ __launch_bounds__(256, 1) void gemm_kernel(float* __restrict__ C)
{
    extern __shared__ char smem[];
    const uint32_t sb = smem_u32(smem);
    const int tid = threadIdx.x, wid = tid >> 5, lane = tid & 31;
    const int bm = blockIdx.x * BM, bn = blockIdx.y * BN;
    const int wm = (wid & 1) * 64;
    const int wn = (wid >> 1) * 64;

    const __half* gAh = g_Ahi + (size_t)bm * KDIM;
    const __half* gAl = g_Alo + (size_t)bm * KDIM;
    const __half* gBh = g_Bhi + (size_t)bn * KDIM;

    const int NK = KDIM / BK;           // 16

    auto load_stage = [&](int kt, int stg) {
        const uint32_t base = sb + stg * STAGE_B;
        const int ke = kt * BK;
#pragma unroll
        for (int i = 0; i < 4; i++) {
            const int chunk = i * 256 + tid;
            const int row = chunk >> 3;
            const int kc = chunk & 7;
            const uint32_t d = SW128(row * 128 + kc * 16);
            const size_t so = (size_t)row * KDIM + ke + kc * 8;
            CP16(base + d,           gAh + so);
            CP16(base + OFF_ALO + d, gAl + so);
        }
#pragma unroll
        for (int i = 0; i < 8; i++) {
            const int chunk = i * 256 + tid;
            const int row = chunk >> 3;
            const int kc = chunk & 7;
            const uint32_t d = SW128(row * 128 + kc * 16);
            CP16(base + OFF_BHI + d, gBh + (size_t)row * KDIM + ke + kc * 8);
        }
        asm volatile("cp.async.commit_group;" ::: "memory");
    };

    load_stage(0, 0);
    load_stage(1, 1);

    float acc[4][8][4] = {};

    const int lrow = lane & 15;
    const int lkb  = (lane >> 4) * 16;
    int offA[4], offB[4];
#pragma unroll
    for (int mt = 0; mt < 4; mt++) offA[mt] = (wm + mt * 16 + lrow) * 128 + lkb;
#pragma unroll
    for (int nt = 0; nt < 4; nt++) offB[nt] = (wn + nt * 16 + lrow) * 128 + lkb;

    int stg = 0;
    for (int kt = 0; kt < NK; kt++) {
        asm volatile("cp.async.wait_group 1;" ::: "memory");
        __syncthreads();
        if (kt + 2 < NK) {
            int s2 = stg + 2; if (s2 >= NSTAGE) s2 -= NSTAGE;
            load_stage(kt + 2, s2);
        }
        const uint32_t base = sb + stg * STAGE_B;

#pragma unroll
        for (int ks = 0; ks < 4; ks++) {
            uint32_t ah[4][4], al[4][4];
#pragma unroll
            for (int mt = 0; mt < 4; mt++) {
                const uint32_t a = base + SW128(offA[mt] + ks * 32);
                LDSM4(ah[mt][0], ah[mt][1], ah[mt][2], ah[mt][3], a);
                LDSM4(al[mt][0], al[mt][1], al[mt][2], al[mt][3], a + OFF_ALO);
            }
            uint32_t b[4][4];
#pragma unroll
            for (int nt = 0; nt < 4; nt++) {
                const uint32_t ba = base + SW128(offB[nt] + ks * 32);
                LDSM4(b[nt][0], b[nt][1], b[nt][2], b[nt][3], ba + OFF_BHI);
            }
#pragma unroll
            for (int mt = 0; mt < 4; mt++)
#pragma unroll
                for (int nt = 0; nt < 4; nt++) {
                    MMA16816(acc[mt][2 * nt + 0], ah[mt], b[nt][0], b[nt][2]);
                    MMA16816(acc[mt][2 * nt + 1], ah[mt], b[nt][1], b[nt][3]);
                }
#pragma unroll
            for (int mt = 0; mt < 4; mt++)
#pragma unroll
                for (int nt = 0; nt < 4; nt++) {
                    MMA16816(acc[mt][2 * nt + 0], al[mt], b[nt][0], b[nt][2]);
                    MMA16816(acc[mt][2 * nt + 1], al[mt], b[nt][1], b[nt][3]);
                }
        }
        if (++stg >= NSTAGE) stg = 0;
    }

    const int er = lane >> 2, ec = (lane & 3) * 2;
#pragma unroll
    for (int mt = 0; mt < 4; mt++) {
#pragma unroll
        for (int nt = 0; nt < 8; nt++) {
            float* c0 = C + (size_t)(bm + wm + mt * 16 + er) * VOCABN
                          + bn + wn + nt * 8 + ec;
            *(float2*)c0 = make_float2(acc[mt][nt][0], acc[mt][nt][1]);
            float* c1 = c0 + (size_t)8 * VOCABN;
            *(float2*)c1 = make_float2(acc[mt][nt][2], acc[mt][nt][3]);
        }
    }
}

// ---------------- softmax + bit projection with exact candidate logits ------
// logit_w = (2*S_k - Z)/Z is invariant to the exp-centering shift, so the
// approximate max is a valid center. For the few candidates above threshold,
// recompute the EXACT fp32 dot tensor[row].weight[v] so softmax weights carry
// fp32 accuracy (fp16x2 GEMM noise ~5e-3 abs would otherwise leak into out 3).
__global__ __launch_bounds__(256) void softmax_bits_kernel(
    const float* __restrict__ logit, const float* __restrict__ tensor,
    const float* __restrict__ weight, float* __restrict__ logit_w)
{
    const int row = blockIdx.x;
    const int tid = threadIdx.x;
    const float4* x4 = (const float4*)(logit + (size_t)row * VOCABN);
    const float4* t4 = (const float4*)(tensor + (size_t)row * KDIM);

    // pass 1: approximate row max
    float m = -FLT_MAX;
    for (int i = tid; i < VOCABN / 4; i += 256) {
        float4 v = x4[i];
        m = fmaxf(m, fmaxf(fmaxf(v.x, v.y), fmaxf(v.z, v.w)));
    }
#pragma unroll
    for (int o = 16; o; o >>= 1) m = fmaxf(m, __shfl_xor_sync(0xffffffffu, m, o));
    __shared__ float smax[8];
    if ((tid & 31) == 0) smax[tid >> 5] = m;
    __syncthreads();
    float mm = smax[0];
#pragma unroll
    for (int w = 1; w < 8; w++) mm = fmaxf(mm, smax[w]);

    // pass 2: thresholded sums; exact fp32 logit per candidate
    const float thr = mm - 20.0f;       // dropped mass <= 32000*e^-20 ~ 7e-5
    float Z = 0.f, S[NBITS];
#pragma unroll
    for (int k = 0; k < NBITS; k++) S[k] = 0.f;

    for (int i = tid; i < VOCABN / 4; i += 256) {
        float4 v = x4[i];
        const float c[4] = {v.x, v.y, v.z, v.w};
#pragma unroll
        for (int j = 0; j < 4; j++) {
            if (c[j] > thr) {
                const int vv = i * 4 + j;
                // exact fp32 dot (deterministic, per-thread)
                const float4* w4 = (const float4*)(weight + (size_t)vv * KDIM);
                float s0 = 0.f, s1 = 0.f, s2 = 0.f, s3 = 0.f;
#pragma unroll 4
                for (int q = 0; q < KDIM / 4; q++) {
                    float4 a = t4[q], b = w4[q];
                    s0 = fmaf(a.x, b.x, s0); s1 = fmaf(a.y, b.y, s1);
                    s2 = fmaf(a.z, b.z, s2); s3 = fmaf(a.w, b.w, s3);
                }
                const float exact = (s0 + s1) + (s2 + s3);
                const float e = __expf(exact - mm);
                Z += e;
#pragma unroll
                for (int k = 0; k < NBITS; k++)
                    if ((vv >> (NBITS - 1 - k)) & 1) S[k] += e;
            }
        }
    }
#pragma unroll
    for (int o = 16; o; o >>= 1) {
        Z += __shfl_xor_sync(0xffffffffu, Z, o);
#pragma unroll
        for (int k = 0; k < NBITS; k++)
            S[k] += __shfl_xor_sync(0xffffffffu, S[k], o);
    }
    __shared__ float red[16][8];
    __shared__ float sfin[16];
    if ((tid & 31) == 0) {
        const int w = tid >> 5;
#pragma unroll
        for (int k = 0; k < NBITS; k++) red[k][w] = S[k];
        red[NBITS][w] = Z;
    }
    __syncthreads();
    if (tid < 16) {
        float s = 0.f;
#pragma unroll
        for (int w = 0; w < 8; w++) s += red[tid][w];
        sfin[tid] = s;
    }
    __syncthreads();
    if (tid < NBITS) {
        const float Zt = sfin[NBITS];
        logit_w[(size_t)row * NBITS + tid] = (2.f * sfin[tid] - Zt) / Zt;
    }
}

// ---------------- launch ----------------------------------------------------
extern "C" void kernel_launch(void* const* d_in, const int* in_sizes, int n_in,
                              void* d_out, int out_size)
{
    const int*   ids        = (const int*)  d_in[0];
    const float* tensor     = (const float*)d_in[1];
    const float* weight     = (const float*)d_in[2];
    const float* weight_bit = (const float*)d_in[3];

    float* out       = (float*)d_out;
    float* out_id    = out;
    float* out_bit   = out + (size_t)MDIM * KDIM;
    float* out_logit = out + (size_t)2 * MDIM * KDIM;
    float* out_lw    = out_logit + (size_t)MDIM * VOCABN;

    cudaFuncSetAttribute(gemm_kernel,
                         cudaFuncAttributeMaxDynamicSharedMemorySize, GEMM_SMEM);

    embed_kernel<<<MDIM, 256>>>(ids, weight, weight_bit, out_id, out_bit);
    split_A_kernel<<<MDIM * KDIM / 1024, 256>>>(tensor);
    split_B_kernel<<<VOCABN * KDIM / 1024, 256>>>(weight);

    dim3 grid(MDIM / BM, VOCABN / BN);  // M fastest -> B-slice L2 reuse
    gemm_kernel<<<grid, 256, GEMM_SMEM>>>(out_logit);

    softmax_bits_kernel<<<MDIM, 256>>>(out_logit, tensor, weight, out_lw);
}

// round 11
// speedup vs baseline: 1.9894x; 1.5145x over previous
#include <cuda_runtime.h>
#include <cuda_fp16.h>
#include <cstdint>
#include <math.h>
#include <float.h>

#define MDIM   4096
#define KDIM   1024
#define VOCABN 32000
#define NBITS  15
#define NWORDS (VOCABN / 32)            // 1000 bitmap words
#define MAXCAND 128

// ---------------- scratch: fp16 splits (A hi/lo, B hi only) -----------------
__device__ __half g_Ahi[(size_t)MDIM * KDIM];
__device__ __half g_Alo[(size_t)MDIM * KDIM];
__device__ __half g_Bhi[(size_t)VOCABN * KDIM];

__device__ __forceinline__ uint32_t smem_u32(const void* p) {
    uint32_t a;
    asm("{ .reg .u64 t; cvta.to.shared.u64 t, %1; cvt.u32.u64 %0, t; }"
        : "=r"(a) : "l"(p));
    return a;
}
#define SW128(o) ((o) ^ (((o) >> 3) & 0x70))

// ---------------- split kernels ---------------------------------------------
__global__ __launch_bounds__(256) void split_A_kernel(const float* __restrict__ src) {
    int i = blockIdx.x * 256 + threadIdx.x;
    float4 v = ((const float4*)src)[i];
    ushort4 h4, l4;
    __half h;
    h = __float2half_rn(v.x); h4.x = __half_as_ushort(h);
    l4.x = __half_as_ushort(__float2half_rn(v.x - __half2float(h)));
    h = __float2half_rn(v.y); h4.y = __half_as_ushort(h);
    l4.y = __half_as_ushort(__float2half_rn(v.y - __half2float(h)));
    h = __float2half_rn(v.z); h4.z = __half_as_ushort(h);
    l4.z = __half_as_ushort(__float2half_rn(v.z - __half2float(h)));
    h = __float2half_rn(v.w); h4.w = __half_as_ushort(h);
    l4.w = __half_as_ushort(__float2half_rn(v.w - __half2float(h)));
    ((ushort4*)g_Ahi)[i] = h4;
    ((ushort4*)g_Alo)[i] = l4;
}
__global__ __launch_bounds__(256) void split_B_kernel(const float* __restrict__ src) {
    int i = blockIdx.x * 256 + threadIdx.x;
    float4 v = ((const float4*)src)[i];
    ushort4 h4;
    h4.x = __half_as_ushort(__float2half_rn(v.x));
    h4.y = __half_as_ushort(__float2half_rn(v.y));
    h4.z = __half_as_ushort(__float2half_rn(v.z));
    h4.w = __half_as_ushort(__float2half_rn(v.w));
    ((ushort4*)g_Bhi)[i] = h4;
}

// ---------------- embed: gather + bit combo ---------------------------------
__global__ __launch_bounds__(256) void embed_kernel(
    const int* __restrict__ ids, const float* __restrict__ weight,
    const float* __restrict__ weight_bit,
    float* __restrict__ out_id, float* __restrict__ out_bit)
{
    const int t = blockIdx.x;
    const int id = ids[t];
    const int d = threadIdx.x * 4;
    float4 w = *(const float4*)(weight + (size_t)id * KDIM + d);
    *(float4*)(out_id + (size_t)t * KDIM + d) = w;
    float4 acc = make_float4(0.f, 0.f, 0.f, 0.f);
#pragma unroll
    for (int j = 0; j < NBITS; j++) {
        const float s = ((id >> (NBITS - 1 - j)) & 1) ? 1.0f : -1.0f;
        float4 wb = *(const float4*)(weight_bit + j * KDIM + d);
        acc.x = fmaf(s, wb.x, acc.x); acc.y = fmaf(s, wb.y, acc.y);
        acc.z = fmaf(s, wb.z, acc.z); acc.w = fmaf(s, wb.w, acc.w);
    }
    *(float4*)(out_bit + (size_t)t * KDIM + d) = acc;
}

// ---------------- fp16x2 GEMM via mma.sync ----------------------------------
#define BM 128
#define BN 256
#define BK 64
#define NSTAGE 3
#define TILE_A (BM * BK * 2)
#define TILE_Bt (BN * BK * 2)
#define OFF_ALO TILE_A
#define OFF_BHI (2 * TILE_A)
#define STAGE_B (2 * TILE_A + TILE_Bt)  // 64 KB
#define GEMM_SMEM (NSTAGE * STAGE_B)    // 192 KB

#define CP16(dst, src) \
    asm volatile("cp.async.cg.shared.global [%0], [%1], 16;" \
                 :: "r"(dst), "l"(src) : "memory")
#define LDSM4(r0, r1, r2, r3, a) \
    asm volatile("ldmatrix.sync.aligned.m8n8.x4.shared.b16 {%0,%1,%2,%3}, [%4];" \
                 : "=r"(r0), "=r"(r1), "=r"(r2), "=r"(r3) : "r"(a))
#define MMA16816(d, a, b0, b1) \
    asm volatile("mma.sync.aligned.m16n8k16.row.col.f32.f16.f16.f32 " \
                 "{%0,%1,%2,%3}, {%4,%5,%6,%7}, {%8,%9}, {%0,%1,%2,%3};" \
                 : "+f"((d)[0]), "+f"((d)[1]), "+f"((d)[2]), "+f"((d)[3]) \
                 : "r"((a)[0]), "r"((a)[1]), "r"((a)[2]), "r"((a)[3]), \
                   "r"(b0), "r"(b1))

__global__ __launch_bounds__(256, 1) void gemm_kernel(float* __restrict__ C)
{
    extern __shared__ char smem[];
    const uint32_t sb = smem_u32(smem);
    const int tid = threadIdx.x, wid = tid >> 5, lane = tid & 31;
    const int bm = blockIdx.x * BM, bn = blockIdx.y * BN;
    const int wm = (wid & 1) * 64;
    const int wn = (wid >> 1) * 64;

    const __half* gAh = g_Ahi + (size_t)bm * KDIM;
    const __half* gAl = g_Alo + (size_t)bm * KDIM;
    const __half* gBh = g_Bhi + (size_t)bn * KDIM;

    const int NK = KDIM / BK;

    auto load_stage = [&](int kt, int stg) {
        const uint32_t base = sb + stg * STAGE_B;
        const int ke = kt * BK;
#pragma unroll
        for (int i = 0; i < 4; i++) {
            const int chunk = i * 256 + tid;
            const int row = chunk >> 3;
            const int kc = chunk & 7;
            const uint32_t d = SW128(row * 128 + kc * 16);
            const size_t so = (size_t)row * KDIM + ke + kc * 8;
            CP16(base + d,           gAh + so);
            CP16(base + OFF_ALO + d, gAl + so);
        }
#pragma unroll
        for (int i = 0; i < 8; i++) {
            const int chunk = i * 256 + tid;
            const int row = chunk >> 3;
            const int kc = chunk & 7;
            const uint32_t d = SW128(row * 128 + kc * 16);
            CP16(base + OFF_BHI + d, gBh + (size_t)row * KDIM + ke + kc * 8);
        }
        asm volatile("cp.async.commit_group;" ::: "memory");
    };

    load_stage(0, 0);
    load_stage(1, 1);

    float acc[4][8][4] = {};

    const int lrow = lane & 15;
    const int lkb  = (lane >> 4) * 16;
    int offA[4], offB[4];
#pragma unroll
    for (int mt = 0; mt < 4; mt++) offA[mt] = (wm + mt * 16 + lrow) * 128 + lkb;
#pragma unroll
    for (int nt = 0; nt < 4; nt++) offB[nt] = (wn + nt * 16 + lrow) * 128 + lkb;

    int stg = 0;
    for (int kt = 0; kt < NK; kt++) {
        asm volatile("cp.async.wait_group 1;" ::: "memory");
        __syncthreads();
        if (kt + 2 < NK) {
            int s2 = stg + 2; if (s2 >= NSTAGE) s2 -= NSTAGE;
            load_stage(kt + 2, s2);
        }
        const uint32_t base = sb + stg * STAGE_B;

#pragma unroll
        for (int ks = 0; ks < 4; ks++) {
            uint32_t ah[4][4], al[4][4];
#pragma unroll
            for (int mt = 0; mt < 4; mt++) {
                const uint32_t a = base + SW128(offA[mt] + ks * 32);
                LDSM4(ah[mt][0], ah[mt][1], ah[mt][2], ah[mt][3], a);
                LDSM4(al[mt][0], al[mt][1], al[mt][2], al[mt][3], a + OFF_ALO);
            }
            uint32_t b[4][4];
#pragma unroll
            for (int nt = 0; nt < 4; nt++) {
                const uint32_t ba = base + SW128(offB[nt] + ks * 32);
                LDSM4(b[nt][0], b[nt][1], b[nt][2], b[nt][3], ba + OFF_BHI);
            }
#pragma unroll
            for (int mt = 0; mt < 4; mt++)
#pragma unroll
                for (int nt = 0; nt < 4; nt++) {
                    MMA16816(acc[mt][2 * nt + 0], ah[mt], b[nt][0], b[nt][2]);
                    MMA16816(acc[mt][2 * nt + 1], ah[mt], b[nt][1], b[nt][3]);
                }
#pragma unroll
            for (int mt = 0; mt < 4; mt++)
#pragma unroll
                for (int nt = 0; nt < 4; nt++) {
                    MMA16816(acc[mt][2 * nt + 0], al[mt], b[nt][0], b[nt][2]);
                    MMA16816(acc[mt][2 * nt + 1], al[mt], b[nt][1], b[nt][3]);
                }
        }
        if (++stg >= NSTAGE) stg = 0;
    }

    const int er = lane >> 2, ec = (lane & 3) * 2;
#pragma unroll
    for (int mt = 0; mt < 4; mt++) {
#pragma unroll
        for (int nt = 0; nt < 8; nt++) {
            float* c0 = C + (size_t)(bm + wm + mt * 16 + er) * VOCABN
                          + bn + wn + nt * 8 + ec;
            *(float2*)c0 = make_float2(acc[mt][nt][0], acc[mt][nt][1]);
            float* c1 = c0 + (size_t)8 * VOCABN;
            *(float2*)c1 = make_float2(acc[mt][nt][2], acc[mt][nt][3]);
        }
    }
}

// ---------------- softmax + bit projection, CTA-cooperative exact dots ------
// Candidates (logit > max-20, ~6/row) collected in a smem bitmap, compacted
// into an ascending deterministic list, then each exact fp32 dot
// tensor[row].weight[v] is computed by ALL 256 threads (one float4 each) with
// a fixed-order reduction. (2S-Z)/Z is shift-invariant, so the noisy max is a
// valid exp center; out3 error = threshold truncation only (~7e-5).
__global__ __launch_bounds__(256) void softmax_bits_kernel(
    const float* __restrict__ logit, const float* __restrict__ tensor,
    const float* __restrict__ weight, float* __restrict__ logit_w)
{
    const int row = blockIdx.x;
    const int tid = threadIdx.x;
    const int lane = tid & 31, wid = tid >> 5;
    const float4* x4 = (const float4*)(logit + (size_t)row * VOCABN);

    __shared__ uint32_t bitmap[NWORDS];
    __shared__ float smax[8];
    __shared__ int s_vcand[MAXCAND];
    __shared__ int s_count;
    __shared__ float s_part[8];
    __shared__ float s_e[MAXCAND];
    __shared__ float sfin[16];

    for (int i = tid; i < NWORDS; i += 256) bitmap[i] = 0u;

    // pass 1: row max
    float m = -FLT_MAX;
    for (int i = tid; i < VOCABN / 4; i += 256) {
        float4 v = x4[i];
        m = fmaxf(m, fmaxf(fmaxf(v.x, v.y), fmaxf(v.z, v.w)));
    }
#pragma unroll
    for (int o = 16; o; o >>= 1) m = fmaxf(m, __shfl_xor_sync(0xffffffffu, m, o));
    if (lane == 0) smax[wid] = m;
    __syncthreads();
    float mm = smax[0];
#pragma unroll
    for (int w = 1; w < 8; w++) mm = fmaxf(mm, smax[w]);

    // pass 2: mark candidates in bitmap (atomicOr: idempotent, order-free)
    const float thr = mm - 20.0f;
    for (int i = tid; i < VOCABN / 4; i += 256) {
        float4 v = x4[i];
        const float c[4] = {v.x, v.y, v.z, v.w};
#pragma unroll
        for (int j = 0; j < 4; j++)
            if (c[j] > thr) {
                const int vv = i * 4 + j;
                atomicOr(&bitmap[vv >> 5], 1u << (vv & 31));
            }
    }
    __syncthreads();

    // compaction by warp 0: ascending deterministic candidate list
    if (wid == 0) {
        const int w0 = lane * 32;                     // up to 32 words per lane
        int cnt = 0;
        for (int w = w0; w < w0 + 32 && w < NWORDS; w++) cnt += __popc(bitmap[w]);
        int pre = cnt;
#pragma unroll
        for (int o = 1; o < 32; o <<= 1) {
            int n = __shfl_up_sync(0xffffffffu, pre, o);
            if (lane >= o) pre += n;
        }
        if (lane == 31) s_count = (pre < MAXCAND) ? pre : MAXCAND;
        int idx = pre - cnt;                          // exclusive prefix
        for (int w = w0; w < w0 + 32 && w < NWORDS; w++) {
            uint32_t bits = bitmap[w];
            while (bits) {
                const int b = __ffs(bits) - 1;
                bits &= bits - 1;
                if (idx < MAXCAND) s_vcand[idx] = w * 32 + b;
                idx++;
            }
        }
    }
    __syncthreads();
    const int cnt = s_count;

    // cooperative exact fp32 dots: one float4 per thread (KDIM/4 == 256)
    const float4 ta = ((const float4*)(tensor + (size_t)row * KDIM))[tid];
    for (int c = 0; c < cnt; c++) {
        const int vv = s_vcand[c];
        const float4 wb = ((const float4*)(weight + (size_t)vv * KDIM))[tid];
        float p = fmaf(ta.x, wb.x, fmaf(ta.y, wb.y, fmaf(ta.z, wb.z, ta.w * wb.w)));
#pragma unroll
        for (int o = 16; o; o >>= 1) p += __shfl_xor_sync(0xffffffffu, p, o);
        if (lane == 0) s_part[wid] = p;
        __syncthreads();
        if (tid == 0) {
            float s = 0.f;
#pragma unroll
            for (int w = 0; w < 8; w++) s += s_part[w];
            s_e[c] = __expf(s - mm);
        }
        __syncthreads();
    }

    // final sums over the ordered candidate list (deterministic)
    if (tid < 16) {
        float s = 0.f;
        for (int c = 0; c < cnt; c++) {
            const float e = s_e[c];
            if (tid == NBITS) s += e;                          // Z
            else if ((s_vcand[c] >> (NBITS - 1 - tid)) & 1) s += e;
        }
        sfin[tid] = s;
    }
    __syncthreads();
    if (tid < NBITS) {
        const float Zt = sfin[NBITS];
        logit_w[(size_t)row * NBITS + tid] = (2.f * sfin[tid] - Zt) / Zt;
    }
}

// ---------------- launch ----------------------------------------------------
extern "C" void kernel_launch(void* const* d_in, const int* in_sizes, int n_in,
                              void* d_out, int out_size)
{
    const int*   ids        = (const int*)  d_in[0];
    const float* tensor     = (const float*)d_in[1];
    const float* weight     = (const float*)d_in[2];
    const float* weight_bit = (const float*)d_in[3];

    float* out       = (float*)d_out;
    float* out_id    = out;
    float* out_bit   = out + (size_t)MDIM * KDIM;
    float* out_logit = out + (size_t)2 * MDIM * KDIM;
    float* out_lw    = out_logit + (size_t)MDIM * VOCABN;

    cudaFuncSetAttribute(gemm_kernel,
                         cudaFuncAttributeMaxDynamicSharedMemorySize, GEMM_SMEM);

    embed_kernel<<<MDIM, 256>>>(ids, weight, weight_bit, out_id, out_bit);
    split_A_kernel<<<MDIM * KDIM / 1024, 256>>>(tensor);
    split_B_kernel<<<VOCABN * KDIM / 1024, 256>>>(weight);

    dim3 grid(MDIM / BM, VOCABN / BN);  // M fastest -> B-slice L2 reuse
    gemm_kernel<<<grid, 256, GEMM_SMEM>>>(out_logit);

    softmax_bits_kernel<<<MDIM, 256>>>(out_logit, tensor, weight, out_lw);
}

// round 12
// speedup vs baseline: 3.2000x; 1.6085x over previous
#include <cuda_runtime.h>
#include <cuda_fp16.h>
#include <cstdint>
#include <math.h>
#include <float.h>

#define MDIM   4096
#define KDIM   1024
#define VOCABN 32000
#define NBITS  15
#define NWORDS (VOCABN / 32)
#define MAXCAND 128

// ---------------- scratch: fp16 conversions ---------------------------------
__device__ __half g_Ah[(size_t)MDIM * KDIM];
__device__ __half g_Bh[(size_t)VOCABN * KDIM];

__device__ __forceinline__ uint32_t smem_u32(const void* p) {
    uint32_t a;
    asm("{ .reg .u64 t; cvta.to.shared.u64 t, %1; cvt.u32.u64 %0, t; }"
        : "=r"(a) : "l"(p));
    return a;
}
#define SW128(o) ((o) ^ (((o) >> 3) & 0x70))

// ---------------- convert kernels (f32 -> fp16) ------------------------------
__global__ __launch_bounds__(256) void conv_A_kernel(const float* __restrict__ src) {
    int i = blockIdx.x * 256 + threadIdx.x;
    float4 v = ((const float4*)src)[i];
    ushort4 h4;
    h4.x = __half_as_ushort(__float2half_rn(v.x));
    h4.y = __half_as_ushort(__float2half_rn(v.y));
    h4.z = __half_as_ushort(__float2half_rn(v.z));
    h4.w = __half_as_ushort(__float2half_rn(v.w));
    ((ushort4*)g_Ah)[i] = h4;
}
__global__ __launch_bounds__(256) void conv_B_kernel(const float* __restrict__ src) {
    int i = blockIdx.x * 256 + threadIdx.x;
    float4 v = ((const float4*)src)[i];
    ushort4 h4;
    h4.x = __half_as_ushort(__float2half_rn(v.x));
    h4.y = __half_as_ushort(__float2half_rn(v.y));
    h4.z = __half_as_ushort(__float2half_rn(v.z));
    h4.w = __half_as_ushort(__float2half_rn(v.w));
    ((ushort4*)g_Bh)[i] = h4;
}

// ---------------- embed: gather + bit combo ---------------------------------
__global__ __launch_bounds__(256) void embed_kernel(
    const int* __restrict__ ids, const float* __restrict__ weight,
    const float* __restrict__ weight_bit,
    float* __restrict__ out_id, float* __restrict__ out_bit)
{
    const int t = blockIdx.x;
    const int id = ids[t];
    const int d = threadIdx.x * 4;
    float4 w = *(const float4*)(weight + (size_t)id * KDIM + d);
    *(float4*)(out_id + (size_t)t * KDIM + d) = w;
    float4 acc = make_float4(0.f, 0.f, 0.f, 0.f);
#pragma unroll
    for (int j = 0; j < NBITS; j++) {
        const float s = ((id >> (NBITS - 1 - j)) & 1) ? 1.0f : -1.0f;
        float4 wb = *(const float4*)(weight_bit + j * KDIM + d);
        acc.x = fmaf(s, wb.x, acc.x); acc.y = fmaf(s, wb.y, acc.y);
        acc.z = fmaf(s, wb.z, acc.z); acc.w = fmaf(s, wb.w, acc.w);
    }
    *(float4*)(out_bit + (size_t)t * KDIM + d) = acc;
}

// ---------------- single-pass fp16 GEMM via mma.sync -------------------------
// C[4096,32000] = Ah[4096,1024] @ Bh[32000,1024]^T  (fp32 accumulate)
// CTA 128x256, 256 threads, warp tile 64x64 (2Mx4N), BK=64, 3-stage cp.async.
#define BM 128
#define BN 256
#define BK 64
#define NSTAGE 3
#define TILE_A (BM * BK * 2)            // 16 KB
#define TILE_Bt (BN * BK * 2)           // 32 KB
#define OFF_BHI TILE_A                  // 16 KB
#define STAGE_B (TILE_A + TILE_Bt)      // 48 KB
#define GEMM_SMEM (NSTAGE * STAGE_B)    // 144 KB

#define CP16(dst, src) \
    asm volatile("cp.async.cg.shared.global [%0], [%1], 16;" \
                 :: "r"(dst), "l"(src) : "memory")
#define LDSM4(r0, r1, r2, r3, a) \
    asm volatile("ldmatrix.sync.aligned.m8n8.x4.shared.b16 {%0,%1,%2,%3}, [%4];" \
                 : "=r"(r0), "=r"(r1), "=r"(r2), "=r"(r3) : "r"(a))
#define MMA16816(d, a, b0, b1) \
    asm volatile("mma.sync.aligned.m16n8k16.row.col.f32.f16.f16.f32 " \
                 "{%0,%1,%2,%3}, {%4,%5,%6,%7}, {%8,%9}, {%0,%1,%2,%3};" \
                 : "+f"((d)[0]), "+f"((d)[1]), "+f"((d)[2]), "+f"((d)[3]) \
                 : "r"((a)[0]), "r"((a)[1]), "r"((a)[2]), "r"((a)[3]), \
                   "r"(b0), "r"(b1))

__global__ __launch_bounds__(256, 1) void gemm_kernel(float* __restrict__ C)
{
    extern __shared__ char smem[];
    const uint32_t sb = smem_u32(smem);
    const int tid = threadIdx.x, wid = tid >> 5, lane = tid & 31;
    const int bm = blockIdx.x * BM, bn = blockIdx.y * BN;
    const int wm = (wid & 1) * 64;
    const int wn = (wid >> 1) * 64;

    const __half* gAh = g_Ah + (size_t)bm * KDIM;
    const __half* gBh = g_Bh + (size_t)bn * KDIM;

    const int NK = KDIM / BK;           // 16

    auto load_stage = [&](int kt, int stg) {
        const uint32_t base = sb + stg * STAGE_B;
        const int ke = kt * BK;
#pragma unroll
        for (int i = 0; i < 4; i++) {
            const int chunk = i * 256 + tid;
            const int row = chunk >> 3;
            const int kc = chunk & 7;
            const uint32_t d = SW128(row * 128 + kc * 16);
            CP16(base + d, gAh + (size_t)row * KDIM + ke + kc * 8);
        }
#pragma unroll
        for (int i = 0; i < 8; i++) {
            const int chunk = i * 256 + tid;
            const int row = chunk >> 3;
            const int kc = chunk & 7;
            const uint32_t d = SW128(row * 128 + kc * 16);
            CP16(base + OFF_BHI + d, gBh + (size_t)row * KDIM + ke + kc * 8);
        }
        asm volatile("cp.async.commit_group;" ::: "memory");
    };

    load_stage(0, 0);
    load_stage(1, 1);

    float acc[4][8][4] = {};

    const int lrow = lane & 15;
    const int lkb  = (lane >> 4) * 16;
    int offA[4], offB[4];
#pragma unroll
    for (int mt = 0; mt < 4; mt++) offA[mt] = (wm + mt * 16 + lrow) * 128 + lkb;
#pragma unroll
    for (int nt = 0; nt < 4; nt++) offB[nt] = (wn + nt * 16 + lrow) * 128 + lkb;

    int stg = 0;
    for (int kt = 0; kt < NK; kt++) {
        asm volatile("cp.async.wait_group 1;" ::: "memory");
        __syncthreads();
        if (kt + 2 < NK) {
            int s2 = stg + 2; if (s2 >= NSTAGE) s2 -= NSTAGE;
            load_stage(kt + 2, s2);
        }
        const uint32_t base = sb + stg * STAGE_B;

#pragma unroll
        for (int ks = 0; ks < 4; ks++) {
            uint32_t ah[4][4];
#pragma unroll
            for (int mt = 0; mt < 4; mt++) {
                const uint32_t a = base + SW128(offA[mt] + ks * 32);
                LDSM4(ah[mt][0], ah[mt][1], ah[mt][2], ah[mt][3], a);
            }
            uint32_t b[4][4];
#pragma unroll
            for (int nt = 0; nt < 4; nt++) {
                const uint32_t ba = base + SW128(offB[nt] + ks * 32);
                LDSM4(b[nt][0], b[nt][1], b[nt][2], b[nt][3], ba + OFF_BHI);
            }
#pragma unroll
            for (int mt = 0; mt < 4; mt++)
#pragma unroll
                for (int nt = 0; nt < 4; nt++) {
                    MMA16816(acc[mt][2 * nt + 0], ah[mt], b[nt][0], b[nt][2]);
                    MMA16816(acc[mt][2 * nt + 1], ah[mt], b[nt][1], b[nt][3]);
                }
        }
        if (++stg >= NSTAGE) stg = 0;
    }

    const int er = lane >> 2, ec = (lane & 3) * 2;
#pragma unroll
    for (int mt = 0; mt < 4; mt++) {
#pragma unroll
        for (int nt = 0; nt < 8; nt++) {
            float* c0 = C + (size_t)(bm + wm + mt * 16 + er) * VOCABN
                          + bn + wn + nt * 8 + ec;
            *(float2*)c0 = make_float2(acc[mt][nt][0], acc[mt][nt][1]);
            float* c1 = c0 + (size_t)8 * VOCABN;
            *(float2*)c1 = make_float2(acc[mt][nt][2], acc[mt][nt][3]);
        }
    }
}

// ---------------- softmax + bit projection, CTA-cooperative exact dots ------
__global__ __launch_bounds__(256) void softmax_bits_kernel(
    const float* __restrict__ logit, const float* __restrict__ tensor,
    const float* __restrict__ weight, float* __restrict__ logit_w)
{
    const int row = blockIdx.x;
    const int tid = threadIdx.x;
    const int lane = tid & 31, wid = tid >> 5;
    const float4* x4 = (const float4*)(logit + (size_t)row * VOCABN);

    __shared__ uint32_t bitmap[NWORDS];
    __shared__ float smax[8];
    __shared__ int s_vcand[MAXCAND];
    __shared__ int s_count;
    __shared__ float s_part[8];
    __shared__ float s_e[MAXCAND];
    __shared__ float sfin[16];

    for (int i = tid; i < NWORDS; i += 256) bitmap[i] = 0u;

    float m = -FLT_MAX;
    for (int i = tid; i < VOCABN / 4; i += 256) {
        float4 v = x4[i];
        m = fmaxf(m, fmaxf(fmaxf(v.x, v.y), fmaxf(v.z, v.w)));
    }
#pragma unroll
    for (int o = 16; o; o >>= 1) m = fmaxf(m, __shfl_xor_sync(0xffffffffu, m, o));
    if (lane == 0) smax[wid] = m;
    __syncthreads();
    float mm = smax[0];
#pragma unroll
    for (int w = 1; w < 8; w++) mm = fmaxf(mm, smax[w]);

    const float thr = mm - 20.0f;
    for (int i = tid; i < VOCABN / 4; i += 256) {
        float4 v = x4[i];
        const float c[4] = {v.x, v.y, v.z, v.w};
#pragma unroll
        for (int j = 0; j < 4; j++)
            if (c[j] > thr) {
                const int vv = i * 4 + j;
                atomicOr(&bitmap[vv >> 5], 1u << (vv & 31));
            }
    }
    __syncthreads();

    if (wid == 0) {
        const int w0 = lane * 32;
        int cnt = 0;
        for (int w = w0; w < w0 + 32 && w < NWORDS; w++) cnt += __popc(bitmap[w]);
        int pre = cnt;
#pragma unroll
        for (int o = 1; o < 32; o <<= 1) {
            int n = __shfl_up_sync(0xffffffffu, pre, o);
            if (lane >= o) pre += n;
        }
        if (lane == 31) s_count = (pre < MAXCAND) ? pre : MAXCAND;
        int idx = pre - cnt;
        for (int w = w0; w < w0 + 32 && w < NWORDS; w++) {
            uint32_t bits = bitmap[w];
            while (bits) {
                const int b = __ffs(bits) - 1;
                bits &= bits - 1;
                if (idx < MAXCAND) s_vcand[idx] = w * 32 + b;
                idx++;
            }
        }
    }
    __syncthreads();
    const int cnt = s_count;

    const float4 ta = ((const float4*)(tensor + (size_t)row * KDIM))[tid];
    for (int c = 0; c < cnt; c++) {
        const int vv = s_vcand[c];
        const float4 wb = ((const float4*)(weight + (size_t)vv * KDIM))[tid];
        float p = fmaf(ta.x, wb.x, fmaf(ta.y, wb.y, fmaf(ta.z, wb.z, ta.w * wb.w)));
#pragma unroll
        for (int o = 16; o; o >>= 1) p += __shfl_xor_sync(0xffffffffu, p, o);
        if (lane == 0) s_part[wid] = p;
        __syncthreads();
        if (tid == 0) {
            float s = 0.f;
#pragma unroll
            for (int w = 0; w < 8; w++) s += s_part[w];
            s_e[c] = __expf(s - mm);
        }
        __syncthreads();
    }

    if (tid < 16) {
        float s = 0.f;
        for (int c = 0; c < cnt; c++) {
            const float e = s_e[c];
            if (tid == NBITS) s += e;
            else if ((s_vcand[c] >> (NBITS - 1 - tid)) & 1) s += e;
        }
        sfin[tid] = s;
    }
    __syncthreads();
    if (tid < NBITS) {
        const float Zt = sfin[NBITS];
        logit_w[(size_t)row * NBITS + tid] = (2.f * sfin[tid] - Zt) / Zt;
    }
}

// ---------------- launch ----------------------------------------------------
extern "C" void kernel_launch(void* const* d_in, const int* in_sizes, int n_in,
                              void* d_out, int out_size)
{
    const int*   ids        = (const int*)  d_in[0];
    const float* tensor     = (const float*)d_in[1];
    const float* weight     = (const float*)d_in[2];
    const float* weight_bit = (const float*)d_in[3];

    float* out       = (float*)d_out;
    float* out_id    = out;
    float* out_bit   = out + (size_t)MDIM * KDIM;
    float* out_logit = out + (size_t)2 * MDIM * KDIM;
    float* out_lw    = out_logit + (size_t)MDIM * VOCABN;

    cudaFuncSetAttribute(gemm_kernel,
                         cudaFuncAttributeMaxDynamicSharedMemorySize, GEMM_SMEM);

    embed_kernel<<<MDIM, 256>>>(ids, weight, weight_bit, out_id, out_bit);
    conv_A_kernel<<<MDIM * KDIM / 1024, 256>>>(tensor);
    conv_B_kernel<<<VOCABN * KDIM / 1024, 256>>>(weight);

    dim3 grid(MDIM / BM, VOCABN / BN);  // M fastest -> B-slice L2 reuse
    gemm_kernel<<<grid, 256, GEMM_SMEM>>>(out_logit);

    softmax_bits_kernel<<<MDIM, 256>>>(out_logit, tensor, weight, out_lw);
}

// round 13
// speedup vs baseline: 3.5139x; 1.0981x over previous
#include <cuda_runtime.h>
#include <cuda_fp16.h>
#include <cstdint>
#include <math.h>
#include <float.h>

#define MDIM   4096
#define KDIM   1024
#define VOCABN 32000
#define NBITS  15
#define NWORDS (VOCABN / 32)
#define MAXCAND 128

// ---------------- scratch ----------------------------------------------------
__device__ __half g_Ah[(size_t)MDIM * KDIM];
__device__ __half g_Bh[(size_t)VOCABN * KDIM];
__device__ uint32_t g_rowmax[MDIM];     // monotone-uint encoded fp32 row max

__device__ __forceinline__ uint32_t smem_u32(const void* p) {
    uint32_t a;
    asm("{ .reg .u64 t; cvta.to.shared.u64 t, %1; cvt.u32.u64 %0, t; }"
        : "=r"(a) : "l"(p));
    return a;
}
#define SW128(o) ((o) ^ (((o) >> 3) & 0x70))

// monotone fp32 <-> uint32 for atomicMax
__device__ __forceinline__ uint32_t fkey(float f) {
    uint32_t u = __float_as_uint(f);
    return (u & 0x80000000u) ? ~u : (u | 0x80000000u);
}
__device__ __forceinline__ float fdec(uint32_t k) {
    return __uint_as_float((k & 0x80000000u) ? (k & 0x7fffffffu) : ~k);
}

// ---------------- init rowmax ------------------------------------------------
__global__ __launch_bounds__(256) void init_rowmax_kernel() {
    g_rowmax[blockIdx.x * 256 + threadIdx.x] = 0u;   // key of -inf class
}

// ---------------- convert kernels (f32 -> fp16) ------------------------------
__global__ __launch_bounds__(256) void conv_A_kernel(const float* __restrict__ src) {
    int i = blockIdx.x * 256 + threadIdx.x;
    float4 v = ((const float4*)src)[i];
    ushort4 h4;
    h4.x = __half_as_ushort(__float2half_rn(v.x));
    h4.y = __half_as_ushort(__float2half_rn(v.y));
    h4.z = __half_as_ushort(__float2half_rn(v.z));
    h4.w = __half_as_ushort(__float2half_rn(v.w));
    ((ushort4*)g_Ah)[i] = h4;
}
__global__ __launch_bounds__(256) void conv_B_kernel(const float* __restrict__ src) {
    int i = blockIdx.x * 256 + threadIdx.x;
    float4 v = ((const float4*)src)[i];
    ushort4 h4;
    h4.x = __half_as_ushort(__float2half_rn(v.x));
    h4.y = __half_as_ushort(__float2half_rn(v.y));
    h4.z = __half_as_ushort(__float2half_rn(v.z));
    h4.w = __half_as_ushort(__float2half_rn(v.w));
    ((ushort4*)g_Bh)[i] = h4;
}

// ---------------- embed: gather + bit combo ---------------------------------
__global__ __launch_bounds__(256) void embed_kernel(
    const int* __restrict__ ids, const float* __restrict__ weight,
    const float* __restrict__ weight_bit,
    float* __restrict__ out_id, float* __restrict__ out_bit)
{
    const int t = blockIdx.x;
    const int id = ids[t];
    const int d = threadIdx.x * 4;
    float4 w = *(const float4*)(weight + (size_t)id * KDIM + d);
    *(float4*)(out_id + (size_t)t * KDIM + d) = w;
    float4 acc = make_float4(0.f, 0.f, 0.f, 0.f);
#pragma unroll
    for (int j = 0; j < NBITS; j++) {
        const float s = ((id >> (NBITS - 1 - j)) & 1) ? 1.0f : -1.0f;
        float4 wb = *(const float4*)(weight_bit + j * KDIM + d);
        acc.x = fmaf(s, wb.x, acc.x); acc.y = fmaf(s, wb.y, acc.y);
        acc.z = fmaf(s, wb.z, acc.z); acc.w = fmaf(s, wb.w, acc.w);
    }
    *(float4*)(out_bit + (size_t)t * KDIM + d) = acc;
}

// ---------------- single-pass fp16 GEMM, 2 CTAs/SM ---------------------------
// C[4096,32000] = Ah @ Bh^T. CTA 128x128, 256 threads, warp tile 64x32
// (2Mx4N), BK=64, 3-stage cp.async (96 KB) -> 2 CTAs/SM decorrelate barrier
// stalls so the tensor pipe stays fed. Epilogue folds per-row max (atomicMax).
#define BM 128
#define BN 128
#define BK 64
#define NSTAGE 3
#define TILE_A (BM * BK * 2)            // 16 KB
#define TILE_Bt (BN * BK * 2)           // 16 KB
#define OFF_B TILE_A
#define STAGE_B (TILE_A + TILE_Bt)      // 32 KB
#define GEMM_SMEM (NSTAGE * STAGE_B)    // 96 KB

#define CP16(dst, src) \
    asm volatile("cp.async.cg.shared.global [%0], [%1], 16;" \
                 :: "r"(dst), "l"(src) : "memory")
#define LDSM4(r0, r1, r2, r3, a) \
    asm volatile("ldmatrix.sync.aligned.m8n8.x4.shared.b16 {%0,%1,%2,%3}, [%4];" \
                 : "=r"(r0), "=r"(r1), "=r"(r2), "=r"(r3) : "r"(a))
#define MMA16816(d, a, b0, b1) \
    asm volatile("mma.sync.aligned.m16n8k16.row.col.f32.f16.f16.f32 " \
                 "{%0,%1,%2,%3}, {%4,%5,%6,%7}, {%8,%9}, {%0,%1,%2,%3};" \
                 : "+f"((d)[0]), "+f"((d)[1]), "+f"((d)[2]), "+f"((d)[3]) \
                 : "r"((a)[0]), "r"((a)[1]), "r"((a)[2]), "r"((a)[3]), \
                   "r"(b0), "r"(b1))

__global__ __launch_bounds__(256, 2) void gemm_kernel(float* __restrict__ C)
{
    extern __shared__ char smem[];
    const uint32_t sb = smem_u32(smem);
    const int tid = threadIdx.x, wid = tid >> 5, lane = tid & 31;
    const int bm = blockIdx.x * BM, bn = blockIdx.y * BN;
    const int wm = (wid & 1) * 64;      // 2 warps in M
    const int wn = (wid >> 1) * 32;     // 4 warps in N

    const __half* gAh = g_Ah + (size_t)bm * KDIM;
    const __half* gBh = g_Bh + (size_t)bn * KDIM;

    const int NK = KDIM / BK;           // 16

    auto load_stage = [&](int kt, int stg) {
        const uint32_t base = sb + stg * STAGE_B;
        const int ke = kt * BK;
#pragma unroll
        for (int i = 0; i < 4; i++) {
            const int chunk = i * 256 + tid;
            const int row = chunk >> 3;
            const int kc = chunk & 7;
            const uint32_t d = SW128(row * 128 + kc * 16);
            const size_t so = (size_t)row * KDIM + ke + kc * 8;
            CP16(base + d,         gAh + so);
            CP16(base + OFF_B + d, gBh + so);
        }
        asm volatile("cp.async.commit_group;" ::: "memory");
    };

    load_stage(0, 0);
    load_stage(1, 1);

    float acc[4][4][4] = {};            // 64 regs: [mt][n8][frag]

    const int lrow = lane & 15;
    const int lkb  = (lane >> 4) * 16;
    int offA[4], offB[2];
#pragma unroll
    for (int mt = 0; mt < 4; mt++) offA[mt] = (wm + mt * 16 + lrow) * 128 + lkb;
#pragma unroll
    for (int nt = 0; nt < 2; nt++) offB[nt] = (wn + nt * 16 + lrow) * 128 + lkb;

    int stg = 0;
    for (int kt = 0; kt < NK; kt++) {
        asm volatile("cp.async.wait_group 1;" ::: "memory");
        __syncthreads();
        if (kt + 2 < NK) {
            int s2 = stg + 2; if (s2 >= NSTAGE) s2 -= NSTAGE;
            load_stage(kt + 2, s2);
        }
        const uint32_t base = sb + stg * STAGE_B;

#pragma unroll
        for (int ks = 0; ks < 4; ks++) {
            uint32_t ah[4][4];
#pragma unroll
            for (int mt = 0; mt < 4; mt++) {
                const uint32_t a = base + SW128(offA[mt] + ks * 32);
                LDSM4(ah[mt][0], ah[mt][1], ah[mt][2], ah[mt][3], a);
            }
            uint32_t b[2][4];
#pragma unroll
            for (int nt = 0; nt < 2; nt++) {
                const uint32_t ba = base + SW128(offB[nt] + ks * 32);
                LDSM4(b[nt][0], b[nt][1], b[nt][2], b[nt][3], ba + OFF_B);
            }
#pragma unroll
            for (int mt = 0; mt < 4; mt++)
#pragma unroll
                for (int nt = 0; nt < 2; nt++) {
                    MMA16816(acc[mt][2 * nt + 0], ah[mt], b[nt][0], b[nt][2]);
                    MMA16816(acc[mt][2 * nt + 1], ah[mt], b[nt][1], b[nt][3]);
                }
        }
        if (++stg >= NSTAGE) stg = 0;
    }

    // epilogue: stores + folded per-row max (atomicMax, order-independent)
    const int er = lane >> 2, ec = (lane & 3) * 2;
#pragma unroll
    for (int mt = 0; mt < 4; mt++) {
        float r0 = -FLT_MAX, r1 = -FLT_MAX;
#pragma unroll
        for (int j = 0; j < 4; j++) {
            float* c0 = C + (size_t)(bm + wm + mt * 16 + er) * VOCABN
                          + bn + wn + j * 8 + ec;
            *(float2*)c0 = make_float2(acc[mt][j][0], acc[mt][j][1]);
            float* c1 = c0 + (size_t)8 * VOCABN;
            *(float2*)c1 = make_float2(acc[mt][j][2], acc[mt][j][3]);
            r0 = fmaxf(r0, fmaxf(acc[mt][j][0], acc[mt][j][1]));
            r1 = fmaxf(r1, fmaxf(acc[mt][j][2], acc[mt][j][3]));
        }
        r0 = fmaxf(r0, __shfl_xor_sync(0xffffffffu, r0, 1));
        r0 = fmaxf(r0, __shfl_xor_sync(0xffffffffu, r0, 2));
        r1 = fmaxf(r1, __shfl_xor_sync(0xffffffffu, r1, 1));
        r1 = fmaxf(r1, __shfl_xor_sync(0xffffffffu, r1, 2));
        if ((lane & 3) == 0) {
            atomicMax(&g_rowmax[bm + wm + mt * 16 + er],     fkey(r0));
            atomicMax(&g_rowmax[bm + wm + mt * 16 + er + 8], fkey(r1));
        }
    }
}

// ---------------- softmax (single logit pass) + exact candidate dots --------
__global__ __launch_bounds__(256) void softmax_bits_kernel(
    const float* __restrict__ logit, const float* __restrict__ tensor,
    const float* __restrict__ weight, float* __restrict__ logit_w)
{
    const int row = blockIdx.x;
    const int tid = threadIdx.x;
    const int lane = tid & 31, wid = tid >> 5;
    const float4* x4 = (const float4*)(logit + (size_t)row * VOCABN);

    __shared__ uint32_t bitmap[NWORDS];
    __shared__ int s_vcand[MAXCAND];
    __shared__ int s_count;
    __shared__ float s_part[8];
    __shared__ float s_e[MAXCAND];
    __shared__ float sfin[16];

    for (int i = tid; i < NWORDS; i += 256) bitmap[i] = 0u;
    __syncthreads();

    const float mm = fdec(g_rowmax[row]);   // computed in GEMM epilogue
    const float thr = mm - 20.0f;           // dropped mass <= 32000*e^-20

    for (int i = tid; i < VOCABN / 4; i += 256) {
        float4 v = x4[i];
        const float c[4] = {v.x, v.y, v.z, v.w};
#pragma unroll
        for (int j = 0; j < 4; j++)
            if (c[j] > thr) {
                const int vv = i * 4 + j;
                atomicOr(&bitmap[vv >> 5], 1u << (vv & 31));
            }
    }
    __syncthreads();

    if (wid == 0) {
        const int w0 = lane * 32;
        int cnt = 0;
        for (int w = w0; w < w0 + 32 && w < NWORDS; w++) cnt += __popc(bitmap[w]);
        int pre = cnt;
#pragma unroll
        for (int o = 1; o < 32; o <<= 1) {
            int n = __shfl_up_sync(0xffffffffu, pre, o);
            if (lane >= o) pre += n;
        }
        if (lane == 31) s_count = (pre < MAXCAND) ? pre : MAXCAND;
        int idx = pre - cnt;
        for (int w = w0; w < w0 + 32 && w < NWORDS; w++) {
            uint32_t bits = bitmap[w];
            while (bits) {
                const int b = __ffs(bits) - 1;
                bits &= bits - 1;
                if (idx < MAXCAND) s_vcand[idx] = w * 32 + b;
                idx++;
            }
        }
    }
    __syncthreads();
    const int cnt = s_count;

    // cooperative exact fp32 dots: one float4 per thread (KDIM/4 == 256)
    const float4 ta = ((const float4*)(tensor + (size_t)row * KDIM))[tid];
    for (int c = 0; c < cnt; c++) {
        const int vv = s_vcand[c];
        const float4 wb = ((const float4*)(weight + (size_t)vv * KDIM))[tid];
        float p = fmaf(ta.x, wb.x, fmaf(ta.y, wb.y, fmaf(ta.z, wb.z, ta.w * wb.w)));
#pragma unroll
        for (int o = 16; o; o >>= 1) p += __shfl_xor_sync(0xffffffffu, p, o);
        if (lane == 0) s_part[wid] = p;
        __syncthreads();
        if (tid == 0) {
            float s = 0.f;
#pragma unroll
            for (int w = 0; w < 8; w++) s += s_part[w];
            s_e[c] = __expf(s - mm);
        }
        __syncthreads();
    }

    if (tid < 16) {
        float s = 0.f;
        for (int c = 0; c < cnt; c++) {
            const float e = s_e[c];
            if (tid == NBITS) s += e;
            else if ((s_vcand[c] >> (NBITS - 1 - tid)) & 1) s += e;
        }
        sfin[tid] = s;
    }
    __syncthreads();
    if (tid < NBITS) {
        const float Zt = sfin[NBITS];
        logit_w[(size_t)row * NBITS + tid] = (2.f * sfin[tid] - Zt) / Zt;
    }
}

// ---------------- launch ----------------------------------------------------
extern "C" void kernel_launch(void* const* d_in, const int* in_sizes, int n_in,
                              void* d_out, int out_size)
{
    const int*   ids        = (const int*)  d_in[0];
    const float* tensor     = (const float*)d_in[1];
    const float* weight     = (const float*)d_in[2];
    const float* weight_bit = (const float*)d_in[3];

    float* out       = (float*)d_out;
    float* out_id    = out;
    float* out_bit   = out + (size_t)MDIM * KDIM;
    float* out_logit = out + (size_t)2 * MDIM * KDIM;
    float* out_lw    = out_logit + (size_t)MDIM * VOCABN;

    cudaFuncSetAttribute(gemm_kernel,
                         cudaFuncAttributeMaxDynamicSharedMemorySize, GEMM_SMEM);

    init_rowmax_kernel<<<MDIM / 256, 256>>>();
    embed_kernel<<<MDIM, 256>>>(ids, weight, weight_bit, out_id, out_bit);
    conv_A_kernel<<<MDIM * KDIM / 1024, 256>>>(tensor);
    conv_B_kernel<<<VOCABN * KDIM / 1024, 256>>>(weight);

    dim3 grid(MDIM / BM, VOCABN / BN);  // M fastest -> B-slice L2 reuse
    gemm_kernel<<<grid, 256, GEMM_SMEM>>>(out_logit);

    softmax_bits_kernel<<<MDIM, 256>>>(out_logit, tensor, weight, out_lw);
}